// round 1
// baseline (speedup 1.0000x reference)
#include <cuda_runtime.h>

// DynamicWeightedMSELoss: scalar mean of w * (input - target)^2 where
//   w = 1 - counts[ch][idx]/total[ch] if round(input*10) lands on the
//   [-10.0 .. 10.0 step 0.1] grid, else 1.0.
//
// Grid membership test collapses exactly to m = rint(x*10) in [-100,100]
// because steps[ch][k] == (k-100)/10.0f and r == m/10.0f are identical
// fp32 computations; off-grid distance is >= 0.1 >> 1e-4 tolerance.

#define NBINS    201
#define NCH      5
#define LUT_SIZE (NBINS * NCH)   // 1005 floats
#define BLOCK    256
#define GRID     1184            // 8 blocks/SM * 148 SMs

__device__ float g_wlut[LUT_SIZE];
__device__ float g_partials[GRID];

// ---------------------------------------------------------------------------
// Kernel 1: build weight LUT. counts is [5, 201] int32 row-major.
// ---------------------------------------------------------------------------
__global__ void build_lut_kernel(const int* __restrict__ counts) {
    __shared__ float s_inv_tot[NCH];
    int tid = threadIdx.x;
    if (tid < NCH) {
        long long s = 0;
        #pragma unroll 1
        for (int k = 0; k < NBINS; ++k) s += counts[tid * NBINS + k];
        s_inv_tot[tid] = 1.0f / (float)s;
    }
    __syncthreads();
    for (int i = tid; i < LUT_SIZE; i += blockDim.x) {
        int ch = i / NBINS;
        g_wlut[i] = 1.0f - (float)counts[i] * s_inv_tot[ch];
    }
}

// ---------------------------------------------------------------------------
// Main kernel: vectorized weighted squared-error partial sums.
// ---------------------------------------------------------------------------
__device__ __forceinline__ float wse_term(float x, float t, int ch,
                                          const float* __restrict__ sw) {
    float d = x - t;
    int   m = __float2int_rn(x * 10.0f);   // round-half-to-even, matches jnp.round
    float w = 1.0f;
    if (m >= -100 && m <= 100) w = sw[ch * NBINS + (m + 100)];
    return w * d * d;
}

__global__ __launch_bounds__(BLOCK)
void mse_kernel(const float4* __restrict__ in4, const float4* __restrict__ tg4,
                int nvec, int ntail,
                const float* __restrict__ in_s, const float* __restrict__ tg_s) {
    __shared__ float sw[LUT_SIZE];
    for (int i = threadIdx.x; i < LUT_SIZE; i += BLOCK) sw[i] = g_wlut[i];
    __syncthreads();

    float acc = 0.0f;
    const int stride = gridDim.x * BLOCK;
    for (int i = blockIdx.x * BLOCK + threadIdx.x; i < nvec; i += stride) {
        float4 x = in4[i];
        float4 t = tg4[i];
        int b  = i * 4;
        int c0 = b % 5;
        int c1 = c0 + 1; if (c1 >= 5) c1 -= 5;
        int c2 = c1 + 1; if (c2 >= 5) c2 -= 5;
        int c3 = c2 + 1; if (c3 >= 5) c3 -= 5;
        acc += wse_term(x.x, t.x, c0, sw);
        acc += wse_term(x.y, t.y, c1, sw);
        acc += wse_term(x.z, t.z, c2, sw);
        acc += wse_term(x.w, t.w, c3, sw);
    }

    // scalar tail (n % 4 elements), handled once
    if (blockIdx.x == 0 && threadIdx.x == 0) {
        for (int j = 0; j < ntail; ++j) {
            int e = nvec * 4 + j;
            acc += wse_term(in_s[e], tg_s[e], e % 5, sw);
        }
    }

    // deterministic block tree-reduce
    __shared__ float sred[BLOCK];
    sred[threadIdx.x] = acc;
    __syncthreads();
    #pragma unroll
    for (int s = BLOCK / 2; s > 0; s >>= 1) {
        if (threadIdx.x < s) sred[threadIdx.x] += sred[threadIdx.x + s];
        __syncthreads();
    }
    if (threadIdx.x == 0) g_partials[blockIdx.x] = sred[0];
}

// ---------------------------------------------------------------------------
// Kernel 3: final reduction of per-block partials (double accumulation).
// ---------------------------------------------------------------------------
__global__ void finalize_kernel(float* __restrict__ out, long long n_total) {
    __shared__ double sd[1024];
    double a = 0.0;
    for (int i = threadIdx.x; i < GRID; i += blockDim.x)
        a += (double)g_partials[i];
    sd[threadIdx.x] = a;
    __syncthreads();
    #pragma unroll
    for (int s = 512; s > 0; s >>= 1) {
        if (threadIdx.x < s) sd[threadIdx.x] += sd[threadIdx.x + s];
        __syncthreads();
    }
    if (threadIdx.x == 0) out[0] = (float)(sd[0] / (double)n_total);
}

// ---------------------------------------------------------------------------
// Launch: d_in[0]=input [B,5] f32, d_in[1]=target [B,5] f32,
//         d_in[2]=steps [5,201] f32 (unused — exact grid), d_in[3]=counts [5,201] i32
// ---------------------------------------------------------------------------
extern "C" void kernel_launch(void* const* d_in, const int* in_sizes, int n_in,
                              void* d_out, int out_size) {
    const float* input  = (const float*)d_in[0];
    const float* target = (const float*)d_in[1];
    const int*   counts = (const int*)d_in[3];
    float* out = (float*)d_out;

    long long n = in_sizes[0];          // B * 5 elements
    int nvec  = (int)(n / 4);
    int ntail = (int)(n % 4);

    build_lut_kernel<<<1, 256>>>(counts);
    mse_kernel<<<GRID, BLOCK>>>((const float4*)input, (const float4*)target,
                                nvec, ntail, input, target);
    finalize_kernel<<<1, 1024>>>(out, n);
}

// round 2
// speedup vs baseline: 1.9604x; 1.9604x over previous
#include <cuda_runtime.h>

// DynamicWeightedMSELoss: scalar mean of w * (input - target)^2 where
//   w = 1 - counts[ch][idx]/total[ch] if round(input*10) lands on the
//   [-10.0 .. 10.0 step 0.1] grid, else 1.0.
//
// Grid membership collapses exactly to m = rint(x*10) in [-100,100] since
// steps[ch][k] == (k-100)/10.0f and r == m/10.0f are bit-identical fp32
// computations; off-grid distance >= 0.1 >> 1e-4 tolerance.
//
// Single fused kernel: per-block LUT build (counts is 4KB, L2-resident) ->
// vectorized grid-stride weighted-SSE -> block tree reduce -> last-block
// double-precision finalize. No separate preamble/epilogue launches.

#define NBINS    201
#define NCH      5
#define LUT_SIZE (NBINS * NCH)   // 1005 floats
#define BLOCK    256
#define GRID     1184            // 8 blocks/SM * 148 SMs

__device__ float        g_partials[GRID];
__device__ unsigned int g_done_count = 0;

__device__ __forceinline__ float wse_term(float x, float t, int ch,
                                          const float* __restrict__ sw) {
    float d = x - t;
    int   m = __float2int_rn(x * 10.0f);   // round-half-to-even, matches jnp.round
    float w = 1.0f;
    if (m >= -100 && m <= 100) w = sw[ch * NBINS + (m + 100)];
    return w * d * d;
}

__global__ __launch_bounds__(BLOCK)
void fused_wmse_kernel(const float4* __restrict__ in4,
                       const float4* __restrict__ tg4,
                       int nvec, int ntail,
                       const float* __restrict__ in_s,
                       const float* __restrict__ tg_s,
                       const int* __restrict__ counts,
                       float* __restrict__ out, long long n_total) {
    __shared__ float sw[LUT_SIZE];
    __shared__ float s_inv[NCH];

    const int tid  = threadIdx.x;
    const int wid  = tid >> 5;
    const int lane = tid & 31;

    // ---- per-block LUT build (counts: [5,201] int32, ~4KB, L2-hot) ----
    if (wid < NCH) {
        long long s = 0;
        #pragma unroll
        for (int k = lane; k < NBINS; k += 32) s += counts[wid * NBINS + k];
        #pragma unroll
        for (int o = 16; o > 0; o >>= 1)
            s += __shfl_down_sync(0xffffffffu, s, o);
        if (lane == 0) s_inv[wid] = 1.0f / (float)s;
    }
    __syncthreads();
    for (int i = tid; i < LUT_SIZE; i += BLOCK) {
        int ch = i / NBINS;
        sw[i] = 1.0f - (float)counts[i] * s_inv[ch];
    }
    __syncthreads();

    // ---- main vectorized loop ----
    float acc = 0.0f;
    const int stride = gridDim.x * BLOCK;
    #pragma unroll 4
    for (int i = blockIdx.x * BLOCK + tid; i < nvec; i += stride) {
        float4 x = in4[i];
        float4 t = tg4[i];
        int c0 = (i * 4) % 5;
        int c1 = c0 + 1; if (c1 >= 5) c1 -= 5;
        int c2 = c1 + 1; if (c2 >= 5) c2 -= 5;
        int c3 = c2 + 1; if (c3 >= 5) c3 -= 5;
        acc += wse_term(x.x, t.x, c0, sw);
        acc += wse_term(x.y, t.y, c1, sw);
        acc += wse_term(x.z, t.z, c2, sw);
        acc += wse_term(x.w, t.w, c3, sw);
    }

    // scalar tail (n % 4 elements), handled once
    if (blockIdx.x == 0 && tid == 0) {
        for (int j = 0; j < ntail; ++j) {
            int e = nvec * 4 + j;
            acc += wse_term(in_s[e], tg_s[e], e % 5, sw);
        }
    }

    // ---- deterministic block tree-reduce ----
    __shared__ float sred[BLOCK];
    sred[tid] = acc;
    __syncthreads();
    #pragma unroll
    for (int s = BLOCK / 2; s > 0; s >>= 1) {
        if (tid < s) sred[tid] += sred[tid + s];
        __syncthreads();
    }

    // ---- last-block finalize (double accumulation, fixed order) ----
    __shared__ bool s_last;
    if (tid == 0) {
        g_partials[blockIdx.x] = sred[0];
        __threadfence();
        unsigned int prev = atomicAdd(&g_done_count, 1u);
        s_last = (prev == (unsigned int)(gridDim.x - 1));
    }
    __syncthreads();

    if (s_last) {
        __shared__ double sd[BLOCK];
        double a = 0.0;
        // fixed strided order -> deterministic across replays
        for (int i = tid; i < GRID; i += BLOCK) a += (double)g_partials[i];
        sd[tid] = a;
        __syncthreads();
        #pragma unroll
        for (int s = BLOCK / 2; s > 0; s >>= 1) {
            if (tid < s) sd[tid] += sd[tid + s];
            __syncthreads();
        }
        if (tid == 0) {
            out[0] = (float)(sd[0] / (double)n_total);
            g_done_count = 0;   // reset for next graph replay
        }
    }
}

// ---------------------------------------------------------------------------
// Launch: d_in[0]=input [B,5] f32, d_in[1]=target [B,5] f32,
//         d_in[2]=steps [5,201] f32 (unused — exact grid), d_in[3]=counts [5,201] i32
// ---------------------------------------------------------------------------
extern "C" void kernel_launch(void* const* d_in, const int* in_sizes, int n_in,
                              void* d_out, int out_size) {
    const float* input  = (const float*)d_in[0];
    const float* target = (const float*)d_in[1];
    const int*   counts = (const int*)d_in[3];
    float* out = (float*)d_out;

    long long n = in_sizes[0];          // B * 5 elements
    int nvec  = (int)(n / 4);
    int ntail = (int)(n % 4);

    fused_wmse_kernel<<<GRID, BLOCK>>>((const float4*)input,
                                       (const float4*)target,
                                       nvec, ntail, input, target,
                                       counts, out, n);
}